// round 4
// baseline (speedup 1.0000x reference)
#include <cuda_runtime.h>
#include <cstdint>

#define NN 50000
#define NE 400000
#define LSEQ 16
#define VOCAB 64
#define EMBD 32
#define HD 128
#define G4 512
#define DD 373
#define DP 384
#define NSID 53
#define IN_COL 161
#define OUT_COL 320

// ------------------------- scratch (static device memory) -------------------
__device__ float      g_P[VOCAB * G4];     // per-token gate init (Wih@emb + bias), gate-major
__device__ float      g_Tb[VOCAB * 32];    // h_bwd(v) @ W1[128:,:] + b1
__device__ ulonglong2 g_W4[32 * 512];      // Whh_f packed: [k4][row], float4 over k
__device__ float      g_xw[NN * DP];       // padded working copy of x (post-scatter)
__device__ float      g_xl[NN * DP];       // x @ Wl + bl
__device__ float      g_xr[NN * DP];       // x @ Wr + br
__device__ float      g_agg[NN * DP];      // attention aggregate
__device__ float      g_ea[NE];            // edge scalar
__device__ float      g_esc[NE];           // edge score -> exp(score - max)
__device__ unsigned   g_emax[NN];          // ordered-uint float max
__device__ float      g_denom[NN];
__device__ int        g_nid[NN];           // argmax of x[:, :53]
__device__ int        g_win[NN * NSID * 2];// last-edge-wins scatter arbitration

// ------------------------- helpers ------------------------------------------
__device__ __forceinline__ float sigm(float x) {
    return __fdividef(1.f, 1.f + __expf(-x));
}
__device__ __forceinline__ float tanha(float x) {
    float y;
    asm("tanh.approx.f32 %0, %1;" : "=f"(y) : "f"(x));
    return y;
}
__device__ __forceinline__ float lrelu(float x) { return x > 0.f ? x : 0.2f * x; }

__device__ __forceinline__ unsigned long long fma2(unsigned long long a,
                                                   unsigned long long b,
                                                   unsigned long long c) {
    unsigned long long d;
    asm("fma.rn.f32x2 %0, %1, %2, %3;" : "=l"(d) : "l"(a), "l"(b), "l"(c));
    return d;
}
__device__ __forceinline__ unsigned long long pk(float lo) {   // (lo, 0)
    return (unsigned long long)__float_as_uint(lo);
}
__device__ __forceinline__ float red(unsigned long long a) {
    return __uint_as_float((unsigned)a) + __uint_as_float((unsigned)(a >> 32));
}

__device__ __forceinline__ unsigned encf(float f) {
    unsigned u = __float_as_uint(f);
    return (u & 0x80000000u) ? ~u : (u | 0x80000000u);
}
__device__ __forceinline__ float decf(unsigned u) {
    return __uint_as_float((u & 0x80000000u) ? (u & 0x7fffffffu) : ~u);
}

// ------------------------- setup: tables -------------------------------------
__global__ void k_tables(const float* __restrict__ embed,
                         const float* __restrict__ Wih_f,
                         const float* __restrict__ bih_f,
                         const float* __restrict__ bhh_f,
                         const float* __restrict__ Whh_f,
                         const float* __restrict__ Wih_r,
                         const float* __restrict__ bih_r,
                         const float* __restrict__ bhh_r,
                         const float* __restrict__ W1,
                         const float* __restrict__ b1)
{
    const int v = blockIdx.x;
    const int tid = threadIdx.x;
    __shared__ float emb_s[EMBD];
    __shared__ float hb_s[HD];

    if (tid < EMBD) emb_s[tid] = (v == 0) ? 0.f : embed[v * EMBD + tid];
    __syncthreads();

    // P[v][r] = emb_v . Wih_f[r] + (bih_f[r] + bhh_f[r])
    {
        const int r = tid;
        float s = bih_f[r] + bhh_f[r];
        #pragma unroll
        for (int k = 0; k < EMBD; k++) s += emb_s[k] * Wih_f[r * EMBD + k];
        g_P[v * G4 + r] = s;
    }

    // pack Whh_f into k-major float4 table: g_W4[k4*512 + r] = W[r][4k4..4k4+3]
    {
        int i = v * 512 + tid;                 // unique in [0, 32768)
        if (i < 16384) {
            int r = i & 511, k4 = i >> 9;
            float4 w = make_float4(Whh_f[r * HD + 4 * k4 + 0],
                                   Whh_f[r * HD + 4 * k4 + 1],
                                   Whh_f[r * HD + 4 * k4 + 2],
                                   Whh_f[r * HD + 4 * k4 + 3]);
            ((float4*)g_W4)[i] = w;
        }
    }

    // h_bwd(v): one cell step from zero state (f-gate irrelevant: c0=0; Whh_r*0 = 0)
    if (tid < HD) {
        const int u = tid;
        float gi = bih_r[u] + bhh_r[u];
        float gg = bih_r[256 + u] + bhh_r[256 + u];
        float go = bih_r[384 + u] + bhh_r[384 + u];
        #pragma unroll
        for (int k = 0; k < EMBD; k++) {
            float e = emb_s[k];
            gi += e * Wih_r[u * EMBD + k];
            gg += e * Wih_r[(256 + u) * EMBD + k];
            go += e * Wih_r[(384 + u) * EMBD + k];
        }
        float cc = sigm(gi) * tanha(gg);
        hb_s[u] = sigm(go) * tanha(cc);
    }
    __syncthreads();

    // Tb[v][f] = hb . W1[128:, f] + b1[f]
    if (tid < 32) {
        const int f = tid;
        float s = b1[f];
        #pragma unroll 8
        for (int k = 0; k < HD; k++) s += hb_s[k] * W1[(128 + k) * 32 + f];
        g_Tb[v * 32 + f] = s;
    }
}

// ------------------------- per-graph init ------------------------------------
__global__ void k_init()
{
    const int i = blockIdx.x * blockDim.x + threadIdx.x;
    const int stride = gridDim.x * blockDim.x;
    for (int j = i; j < NN * DP; j += stride) g_agg[j] = 0.f;
    for (int j = i; j < NN; j += stride) { g_emax[j] = 0u; g_denom[j] = 0.f; }
    for (int j = i; j < NN * NSID * 2; j += stride) g_win[j] = -1;
}

// ------------------------- LSTM + MLP edge scalar ----------------------------
// 512 threads, 32 edges/block. thread: unit u = tid&127, edge-group eo = tid>>7,
// handles edges eo+4j (8 edges). Input GEMM is a table lookup (g_P). Recurrence
// uses packed fma.rn.f32x2 over adjacent k.
__global__ __launch_bounds__(512, 1) void k_lstm(const int* __restrict__ tokens,
                                                 const float* __restrict__ W1,
                                                 const float* __restrict__ W2,
                                                 const float* __restrict__ b2)
{
    __shared__ __align__(16) float Hs[32][HD];
    __shared__ int   tok_s[32][LSEQ];
    __shared__ float Fs[32][33];

    const int tid = threadIdx.x;
    const int u = tid & 127;
    const int eo = tid >> 7;
    const int ebase = blockIdx.x * 32;

    { int e = tid >> 4, t = tid & 15; tok_s[e][t] = tokens[(ebase + e) * LSEQ + t]; }
    for (int i = tid; i < 32 * HD; i += 512) (&Hs[0][0])[i] = 0.f;
    __syncthreads();

    float c[8];
    #pragma unroll
    for (int j = 0; j < 8; j++) c[j] = 0.f;

    unsigned long long a0[8], a1[8], a2[8], a3[8];

    for (int t = 0; t < LSEQ; t++) {
        #pragma unroll
        for (int j = 0; j < 8; j++) {
            const float* Pv = g_P + tok_s[eo + 4 * j][t] * G4 + u;
            a0[j] = pk(Pv[0]);
            a1[j] = pk(Pv[128]);
            a2[j] = pk(Pv[256]);
            a3[j] = pk(Pv[384]);
        }
        const ulonglong2* wb = g_W4 + u;
        #pragma unroll 2
        for (int k4 = 0; k4 < 32; k4++) {
            ulonglong2 w0 = wb[0], w1 = wb[128], w2 = wb[256], w3 = wb[384];
            #pragma unroll
            for (int j = 0; j < 8; j++) {
                ulonglong2 h2 = *(const ulonglong2*)(&Hs[eo + 4 * j][k4 * 4]);
                a0[j] = fma2(h2.x, w0.x, a0[j]); a0[j] = fma2(h2.y, w0.y, a0[j]);
                a1[j] = fma2(h2.x, w1.x, a1[j]); a1[j] = fma2(h2.y, w1.y, a1[j]);
                a2[j] = fma2(h2.x, w2.x, a2[j]); a2[j] = fma2(h2.y, w2.y, a2[j]);
                a3[j] = fma2(h2.x, w3.x, a3[j]); a3[j] = fma2(h2.y, w3.y, a3[j]);
            }
            wb += 512;
        }
        float hnew[8];
        #pragma unroll
        for (int j = 0; j < 8; j++) {
            float ig = sigm(red(a0[j]));
            float fg = sigm(red(a1[j]));
            float gg = tanha(red(a2[j]));
            float og = sigm(red(a3[j]));
            c[j] = fg * c[j] + ig * gg;
            hnew[j] = og * tanha(c[j]);
        }
        __syncthreads();
        #pragma unroll
        for (int j = 0; j < 8; j++) Hs[eo + 4 * j][u] = hnew[j];
        __syncthreads();
    }

    // MLP head: feat = relu(h_fwd @ W1[:128] + Tb[last_tok]); scalar = relu(feat @ W2 + b2)
    {
        const int f = tid & 31;
        const int er = tid >> 5;        // 0..15
        #pragma unroll
        for (int hh = 0; hh < 2; hh++) {
            int e = er + 16 * hh;
            float s = g_Tb[tok_s[e][LSEQ - 1] * 32 + f];
            #pragma unroll 8
            for (int k = 0; k < HD; k++) s += Hs[e][k] * W1[k * 32 + f];
            Fs[e][f] = fmaxf(s, 0.f);
        }
    }
    __syncthreads();
    if (tid < 32) {
        float s = b2[0];
        #pragma unroll
        for (int f = 0; f < 32; f++) s += Fs[tid][f] * W2[f];
        g_ea[ebase + tid] = fmaxf(s, 0.f);
    }
}

// ------------------------- node argmax (first 53 cols, first-max wins) -------
__global__ void k_argmax(const float* __restrict__ x)
{
    const int gw = (blockIdx.x * blockDim.x + threadIdx.x) >> 5;
    const int lane = threadIdx.x & 31;
    if (gw >= NN) return;
    const float* row = x + (size_t)gw * DD;
    float best = -3.4e38f;
    int bidx = 0x7fffffff;
    for (int i = lane; i < NSID; i += 32) {
        float v = row[i];
        if (v > best) { best = v; bidx = i; }
    }
    #pragma unroll
    for (int off = 16; off; off >>= 1) {
        float ov = __shfl_down_sync(0xffffffffu, best, off);
        int oi = __shfl_down_sync(0xffffffffu, bidx, off);
        if (ov > best || (ov == best && oi < bidx)) { best = ov; bidx = oi; }
    }
    if (lane == 0) g_nid[gw] = bidx;
}

// ------------------------- copy x into padded workspace ----------------------
__global__ void k_copy(const float* __restrict__ x)
{
    const int i = blockIdx.x * blockDim.x + threadIdx.x;
    const int stride = gridDim.x * blockDim.x;
    for (int idx = i; idx < NN * DP; idx += stride) {
        int n = idx / DP, d = idx - n * DP;
        g_xw[idx] = (d < DD) ? x[n * DD + d] : 0.f;
    }
}

// ------------------------- scatter writes (last edge index wins) -------------
__global__ void k_win(const int* __restrict__ ei)
{
    const int e = blockIdx.x * blockDim.x + threadIdx.x;
    if (e >= NE) return;
    int src = ei[e], dst = ei[NE + e];
    atomicMax(&g_win[dst * NSID + g_nid[src]], e);
    atomicMax(&g_win[NN * NSID + src * NSID + g_nid[dst]], e);
}

__global__ void k_wr(const int* __restrict__ ei)
{
    const int e = blockIdx.x * blockDim.x + threadIdx.x;
    if (e >= NE) return;
    int src = ei[e], dst = ei[NE + e];
    int sid = g_nid[src], tgt = g_nid[dst];
    float v = g_ea[e];
    if (g_win[dst * NSID + sid] == e)             g_xw[(size_t)dst * DP + IN_COL + sid] = v;
    if (g_win[NN * NSID + src * NSID + tgt] == e) g_xw[(size_t)src * DP + OUT_COL + tgt] = v;
}

// ------------------------- GEMM: C = xw @ B + bias (pads -> 0) ---------------
#define BM 64
#define BN 64
#define BK 16
__global__ __launch_bounds__(256) void k_gemm(const float* __restrict__ B,
                                              const float* __restrict__ bias,
                                              int sel)
{
    __shared__ __align__(16) float As[BK * BM];
    __shared__ __align__(16) float Bs[BK * BN];
    float* C = sel ? g_xr : g_xl;
    const int tid = threadIdx.x;
    const int mBase = blockIdx.y * BM;
    const int nBase = blockIdx.x * BN;
    const int ty = tid >> 4, tx = tid & 15;
    const int arow = tid >> 2;
    const int akq = tid & 3;
    const float4* As4 = (const float4*)As;
    const float4* Bs4 = (const float4*)Bs;

    float acc[4][4];
    #pragma unroll
    for (int i = 0; i < 4; i++)
        #pragma unroll
        for (int j = 0; j < 4; j++) acc[i][j] = 0.f;

    for (int k0 = 0; k0 < DD; k0 += BK) {
        int gm = mBase + arow;
        float4 av = make_float4(0.f, 0.f, 0.f, 0.f);
        if (gm < NN) av = *(const float4*)(g_xw + (size_t)gm * DP + k0 + akq * 4);
        As[(akq * 4 + 0) * BM + arow] = av.x;
        As[(akq * 4 + 1) * BM + arow] = av.y;
        As[(akq * 4 + 2) * BM + arow] = av.z;
        As[(akq * 4 + 3) * BM + arow] = av.w;
        #pragma unroll
        for (int i = 0; i < 4; i++) {
            int idx = tid + 256 * i;
            int kk = idx >> 6, jj = idx & 63;
            int gk = k0 + kk, gj = nBase + jj;
            Bs[idx] = (gk < DD && gj < DD) ? B[gk * DD + gj] : 0.f;
        }
        __syncthreads();
        #pragma unroll
        for (int kk = 0; kk < BK; kk++) {
            float4 a = As4[kk * 16 + ty];
            float4 b = Bs4[kk * 16 + tx];
            acc[0][0] += a.x * b.x; acc[0][1] += a.x * b.y; acc[0][2] += a.x * b.z; acc[0][3] += a.x * b.w;
            acc[1][0] += a.y * b.x; acc[1][1] += a.y * b.y; acc[1][2] += a.y * b.z; acc[1][3] += a.y * b.w;
            acc[2][0] += a.z * b.x; acc[2][1] += a.z * b.y; acc[2][2] += a.z * b.z; acc[2][3] += a.z * b.w;
            acc[3][0] += a.w * b.x; acc[3][1] += a.w * b.y; acc[3][2] += a.w * b.z; acc[3][3] += a.w * b.w;
        }
        __syncthreads();
    }
    #pragma unroll
    for (int i = 0; i < 4; i++) {
        int gm = mBase + ty * 4 + i;
        if (gm >= NN) continue;
        #pragma unroll
        for (int j = 0; j < 4; j++) {
            int gj = nBase + tx * 4 + j;
            float bv = (gj < DD) ? bias[gj] : 0.f;
            C[(size_t)gm * DP + gj] = acc[i][j] + bv;
        }
    }
}

// ------------------------- GATv2 edge passes ---------------------------------
__global__ void k_score(const int* __restrict__ ei, const float* __restrict__ att)
{
    const int gw = (blockIdx.x * blockDim.x + threadIdx.x) >> 5;
    const int lane = threadIdx.x & 31;
    if (gw >= NE) return;
    int src = ei[gw], dst = ei[NE + gw];
    const float4* pl = (const float4*)(g_xl + (size_t)src * DP);
    const float4* pr = (const float4*)(g_xr + (size_t)dst * DP);
    float s = 0.f;
    #pragma unroll
    for (int i = 0; i < 3; i++) {
        int c4 = lane + 32 * i;
        float4 a = pl[c4];
        float4 b = pr[c4];
        float4 m;
        m.x = lrelu(a.x + b.x); m.y = lrelu(a.y + b.y);
        m.z = lrelu(a.z + b.z); m.w = lrelu(a.w + b.w);
        int cc = c4 * 4;
        if (cc + 3 < DD) {
            s += m.x * att[cc] + m.y * att[cc + 1] + m.z * att[cc + 2] + m.w * att[cc + 3];
        } else {
            if (cc     < DD) s += m.x * att[cc];
            if (cc + 1 < DD) s += m.y * att[cc + 1];
            if (cc + 2 < DD) s += m.z * att[cc + 2];
        }
    }
    #pragma unroll
    for (int off = 16; off; off >>= 1) s += __shfl_xor_sync(0xffffffffu, s, off);
    if (lane == 0) {
        g_esc[gw] = s;
        atomicMax(&g_emax[dst], encf(s));
    }
}

__global__ void k_exp(const int* __restrict__ ei)
{
    const int e = blockIdx.x * blockDim.x + threadIdx.x;
    if (e >= NE) return;
    int dst = ei[NE + e];
    float mx = decf(g_emax[dst]);
    float ex = __expf(g_esc[e] - mx);
    g_esc[e] = ex;
    atomicAdd(&g_denom[dst], ex);
}

__global__ void k_agg(const int* __restrict__ ei)
{
    const int gw = (blockIdx.x * blockDim.x + threadIdx.x) >> 5;
    const int lane = threadIdx.x & 31;
    if (gw >= NE) return;
    int src = ei[gw], dst = ei[NE + gw];
    float alpha = g_esc[gw] / (g_denom[dst] + 1e-16f);
    const float4* pl = (const float4*)(g_xl + (size_t)src * DP);
    float* pa = g_agg + (size_t)dst * DP;
    #pragma unroll
    for (int i = 0; i < 3; i++) {
        int c4 = lane + 32 * i;
        float4 v = pl[c4];
        atomicAdd(pa + c4 * 4 + 0, alpha * v.x);
        atomicAdd(pa + c4 * 4 + 1, alpha * v.y);
        atomicAdd(pa + c4 * 4 + 2, alpha * v.z);
        atomicAdd(pa + c4 * 4 + 3, alpha * v.w);
    }
}

// ------------------------- epilogue ------------------------------------------
__global__ void k_out(const float* __restrict__ bias, float* __restrict__ out, int half)
{
    const int i = blockIdx.x * blockDim.x + threadIdx.x;
    const int stride = gridDim.x * blockDim.x;
    for (int idx = i; idx < NN * DD; idx += stride) {
        int n = idx / DD, d = idx - n * DD;
        float v = g_agg[n * DP + d] + bias[d] + g_xw[n * DP + d];
        out[(size_t)n * (2 * DD) + half * DD + d] = fmaxf(v, 0.f);
    }
}

// ------------------------- launch --------------------------------------------
extern "C" void kernel_launch(void* const* d_in, const int* in_sizes, int n_in,
                              void* d_out, int out_size)
{
    (void)in_sizes; (void)n_in; (void)out_size;
    const float* fx    = (const float*)d_in[0];
    const float* bx    = (const float*)d_in[1];
    const int*   f_ei  = (const int*)d_in[2];
    const int*   b_ei  = (const int*)d_in[3];
    const int*   f_tok = (const int*)d_in[4];
    const int*   b_tok = (const int*)d_in[5];
    const float* embed = (const float*)d_in[6];
    const float* Wih_f = (const float*)d_in[7];
    const float* Whh_f = (const float*)d_in[8];
    const float* bih_f = (const float*)d_in[9];
    const float* bhh_f = (const float*)d_in[10];
    const float* Wih_r = (const float*)d_in[11];
    const float* bih_r = (const float*)d_in[13];
    const float* bhh_r = (const float*)d_in[14];
    const float* W1    = (const float*)d_in[15];
    const float* b1    = (const float*)d_in[16];
    const float* W2    = (const float*)d_in[17];
    const float* b2    = (const float*)d_in[18];
    float* out = (float*)d_out;

    k_tables<<<VOCAB, 512>>>(embed, Wih_f, bih_f, bhh_f, Whh_f, Wih_r, bih_r, bhh_r, W1, b1);

    for (int g = 0; g < 2; g++) {
        const float* x    = g ? bx : fx;
        const int*   ei   = g ? b_ei : f_ei;
        const int*   tok  = g ? b_tok : f_tok;
        const float* Wl   = (const float*)d_in[19 + 6 * g + 0];
        const float* bl   = (const float*)d_in[19 + 6 * g + 1];
        const float* Wr   = (const float*)d_in[19 + 6 * g + 2];
        const float* br   = (const float*)d_in[19 + 6 * g + 3];
        const float* att  = (const float*)d_in[19 + 6 * g + 4];
        const float* bias = (const float*)d_in[19 + 6 * g + 5];

        k_init<<<1024, 256>>>();
        k_lstm<<<NE / 32, 512>>>(tok, W1, W2, b2);
        k_argmax<<<(NN * 32 + 255) / 256, 256>>>(x);
        k_copy<<<2048, 256>>>(x);
        k_win<<<(NE + 255) / 256, 256>>>(ei);
        k_wr<<<(NE + 255) / 256, 256>>>(ei);
        dim3 ggrid(DP / BN, (NN + BM - 1) / BM);
        k_gemm<<<ggrid, 256>>>(Wl, bl, 0);
        k_gemm<<<ggrid, 256>>>(Wr, br, 1);
        k_score<<<NE / 8, 256>>>(ei, att);
        k_exp<<<(NE + 255) / 256, 256>>>(ei);
        k_agg<<<NE / 8, 256>>>(ei);
        k_out<<<4096, 256>>>(bias, out, g);
    }
}

// round 10
// speedup vs baseline: 4.1033x; 4.1033x over previous
#include <cuda_runtime.h>
#include <cuda_bf16.h>
#include <cstdint>

#define NN 50000
#define NE 400000
#define LSEQ 16
#define VOCAB 64
#define EMBD 32
#define HD 128
#define G4 512
#define DD 373
#define DP 384
#define NSID 53
#define IN_COL 161
#define OUT_COL 320

#define EPB 64                  // edges per lstm block
#define LSTM_THREADS 512
#define PITCH 272               // smem row pitch bytes (136 bf16): conflict-free ldmatrix

// ------------------------- scratch (static device memory) -------------------
__device__ float          g_P[VOCAB * G4];   // per-token gate init (Wih@emb + bias)
__device__ float          g_Tb[VOCAB * 32];  // h_bwd(v) @ W1[128:,:] + b1
__device__ __nv_bfloat16  g_WBh[G4 * HD];    // Whh bf16, row-major [n][k]
__device__ float          g_xw[NN * DP];     // padded working copy of x (post-scatter)
__device__ float          g_xl[NN * DP];     // x @ Wl + bl
__device__ float          g_xr[NN * DP];     // x @ Wr + br
__device__ float          g_agg[NN * DP];    // attention aggregate
__device__ float          g_ea[NE];          // edge scalar
__device__ float          g_esc[NE];         // edge score -> exp(score - max)
__device__ unsigned       g_emax[NN];        // ordered-uint float max
__device__ float          g_denom[NN];
__device__ int            g_nid[NN];         // argmax of x[:, :53]
__device__ int            g_win[NN * NSID * 2]; // last-edge-wins arbitration

// ------------------------- helpers ------------------------------------------
__device__ __forceinline__ float sigm(float x) {
    return __fdividef(1.f, 1.f + __expf(-x));
}
__device__ __forceinline__ float tanha(float x) {
    float y;
    asm("tanh.approx.f32 %0, %1;" : "=f"(y) : "f"(x));
    return y;
}
// sigmoid(x) = 0.5*tanh(0.5x) + 0.5  (one MUFU)
__device__ __forceinline__ float sigt(float x) {
    return fmaf(0.5f, tanha(0.5f * x), 0.5f);
}
__device__ __forceinline__ float lrelu(float x) { return x > 0.f ? x : 0.2f * x; }

__device__ __forceinline__ unsigned encf(float f) {
    unsigned u = __float_as_uint(f);
    return (u & 0x80000000u) ? ~u : (u | 0x80000000u);
}
__device__ __forceinline__ float decf(unsigned u) {
    return __uint_as_float((u & 0x80000000u) ? (u & 0x7fffffffu) : ~u);
}
__device__ __forceinline__ uint32_t su32(const void* p) {
    uint32_t a;
    asm("{ .reg .u64 t; cvta.to.shared.u64 t, %1; cvt.u32.u64 %0, t; }"
        : "=r"(a) : "l"(p));
    return a;
}
__device__ __forceinline__ void ldsm4(uint32_t* r, uint32_t addr) {
    asm volatile("ldmatrix.sync.aligned.m8n8.x4.shared.b16 {%0,%1,%2,%3}, [%4];"
                 : "=r"(r[0]), "=r"(r[1]), "=r"(r[2]), "=r"(r[3]) : "r"(addr));
}
__device__ __forceinline__ void ldsm4t(uint32_t* r, uint32_t addr) {
    asm volatile("ldmatrix.sync.aligned.m8n8.x4.trans.shared.b16 {%0,%1,%2,%3}, [%4];"
                 : "=r"(r[0]), "=r"(r[1]), "=r"(r[2]), "=r"(r[3]) : "r"(addr));
}
__device__ __forceinline__ void mma16816(float* d, const uint32_t* a,
                                         uint32_t b0, uint32_t b1) {
    asm volatile(
        "mma.sync.aligned.m16n8k16.row.col.f32.bf16.bf16.f32 "
        "{%0,%1,%2,%3}, {%4,%5,%6,%7}, {%8,%9}, {%0,%1,%2,%3};"
        : "+f"(d[0]), "+f"(d[1]), "+f"(d[2]), "+f"(d[3])
        : "r"(a[0]), "r"(a[1]), "r"(a[2]), "r"(a[3]), "r"(b0), "r"(b1));
}

// smem layout for k_lstm (dynamic)
#define OFF_W    0                         // 512*272 = 139264
#define OFF_H    139264                    // 64*272  = 17408
#define OFF_TOK  156672                    // 64*17*4 = 4352
#define OFF_FS   161024                    // 64*33*4 = 8448
#define LSTM_SMEM 169472

// ------------------------- setup: tables -------------------------------------
__global__ void k_tables(const float* __restrict__ embed,
                         const float* __restrict__ Wih_f,
                         const float* __restrict__ bih_f,
                         const float* __restrict__ bhh_f,
                         const float* __restrict__ Whh_f,
                         const float* __restrict__ Wih_r,
                         const float* __restrict__ bih_r,
                         const float* __restrict__ bhh_r,
                         const float* __restrict__ W1,
                         const float* __restrict__ b1)
{
    const int v = blockIdx.x;
    const int tid = threadIdx.x;
    __shared__ float emb_s[EMBD];
    __shared__ float hb_s[HD];

    if (tid < EMBD) emb_s[tid] = (v == 0) ? 0.f : embed[v * EMBD + tid];
    __syncthreads();

    // P[v][r] = emb_v . Wih_f[r] + (bih_f[r] + bhh_f[r]), r = gate*128 + unit
    {
        const int r = tid;
        float s = bih_f[r] + bhh_f[r];
        #pragma unroll
        for (int k = 0; k < EMBD; k++) s += emb_s[k] * Wih_f[r * EMBD + k];
        g_P[v * G4 + r] = s;
    }

    // Whh -> bf16 row-major
    {
        #pragma unroll
        for (int rep = 0; rep < 2; rep++) {
            int i = v * 512 + tid + rep * 32768;   // [0, 65536)
            g_WBh[i] = __float2bfloat16(Whh_f[i]);
        }
    }

    // h_bwd(v): one cell step from zero state (c0=0 -> f-gate dead; Whh_r*0 = 0)
    if (tid < HD) {
        const int u = tid;
        float gi = bih_r[u] + bhh_r[u];
        float gg = bih_r[256 + u] + bhh_r[256 + u];
        float go = bih_r[384 + u] + bhh_r[384 + u];
        #pragma unroll
        for (int k = 0; k < EMBD; k++) {
            float e = emb_s[k];
            gi += e * Wih_r[u * EMBD + k];
            gg += e * Wih_r[(256 + u) * EMBD + k];
            go += e * Wih_r[(384 + u) * EMBD + k];
        }
        float cc = sigm(gi) * tanha(gg);
        hb_s[u] = sigm(go) * tanha(cc);
    }
    __syncthreads();

    // Tb[v][f] = hb . W1[128:, f] + b1[f]
    if (tid < 32) {
        const int f = tid;
        float s = b1[f];
        #pragma unroll 8
        for (int k = 0; k < HD; k++) s += hb_s[k] * W1[(128 + k) * 32 + f];
        g_Tb[v * 32 + f] = s;
    }
}

// ------------------------- per-graph init ------------------------------------
__global__ void k_init()
{
    const int i = blockIdx.x * blockDim.x + threadIdx.x;
    const int stride = gridDim.x * blockDim.x;
    for (int j = i; j < NN * DP; j += stride) g_agg[j] = 0.f;
    for (int j = i; j < NN; j += stride) { g_emax[j] = 0u; g_denom[j] = 0.f; }
    for (int j = i; j < NN * NSID * 2; j += stride) g_win[j] = -1;
}

// ------------------------- LSTM via mma.sync (HMMA bf16) ---------------------
// 64 edges/block, 512 threads = 16 warps. warp = edge-tile(4) x unit-group(4).
// Per step: D[64,512] = H[64,128] @ Whh^T (bf16, fp32 accum in regs).
// Each warp owns all 4 gates of its 32 units -> c/h update is warp-local.
__global__ __launch_bounds__(LSTM_THREADS, 1)
void k_lstm(const int* __restrict__ tokens,
            const float* __restrict__ W1,
            const float* __restrict__ W2,
            const float* __restrict__ b2)
{
    extern __shared__ __align__(16) char smem[];
    const uint32_t sbase = su32(smem);
    const int tid = threadIdx.x;
    const int wid = tid >> 5;
    const int lane = tid & 31;
    const int ebase = blockIdx.x * EPB;

    int* tok_s = (int*)(smem + OFF_TOK);          // [64][17]
    float* Fs = (float*)(smem + OFF_FS);          // [64][33]

    // stage weights into pitched smem, zero H, stage tokens
    {
        const uint4* src = (const uint4*)g_WBh;   // [512][128] bf16 = 8192 uint4
        #pragma unroll
        for (int r = 0; r < 16; r++) {
            int idx = tid + r * LSTM_THREADS;     // [0, 8192)
            int row = idx >> 4, q = idx & 15;
            *(uint4*)(smem + OFF_W + row * PITCH + q * 16) = src[idx];
        }
        #pragma unroll
        for (int r = 0; r < 3; r++) {
            int idx = tid + r * LSTM_THREADS;
            if (idx < 1088) *(uint4*)(smem + OFF_H + idx * 16) = make_uint4(0, 0, 0, 0);
        }
        #pragma unroll
        for (int r = 0; r < 2; r++) {
            int idx = tid + r * LSTM_THREADS;     // [0, 1024)
            int e = idx >> 4, t = idx & 15;
            tok_s[e * 17 + t] = tokens[(ebase + e) * LSEQ + t];
        }
    }
    __syncthreads();

    const int et = wid & 3;                 // edge tile: rows et*16..+15
    const int ug = wid >> 2;                // unit group: units ug*32..+31
    const int t4 = lane & 3;
    const int g8 = lane >> 2;               // 0..7
    const int row0 = et * 16 + g8;          // local edge of d0/d1
    const int row1 = row0 + 8;              // local edge of d2/d3

    // ldmatrix lane addresses (constant across steps)
    const uint32_t aAddr = sbase + OFF_H +
        (uint32_t)(et * 16 + (lane & 15)) * PITCH + (uint32_t)((lane >> 4) << 3) * 2;
    // B: n = n0 + (lane&7) + ((lane&16)?8:0); kk = (lane&8)?8:0
    const uint32_t bLane = (uint32_t)((lane & 7) + ((lane & 16) ? 8 : 0)) * PITCH +
                           (uint32_t)((lane & 8) ? 8 : 0) * 2;

    float c[16];
    #pragma unroll
    for (int j = 0; j < 16; j++) c[j] = 0.f;

    for (int t = 0; t < LSEQ; t++) {
        float acc[8][8];
        #pragma unroll
        for (int np = 0; np < 8; np++)
            #pragma unroll
            for (int j = 0; j < 8; j++) acc[np][j] = 0.f;

        #pragma unroll
        for (int k = 0; k < 8; k++) {
            uint32_t a[4];
            ldsm4(a, aAddr + (uint32_t)(k * 16) * 2);
            #pragma unroll
            for (int np = 0; np < 8; np++) {
                const int gate = np >> 1, uh = np & 1;
                const int n0 = gate * 128 + ug * 32 + uh * 16;
                uint32_t b[4];
                ldsm4t(b, sbase + OFF_W + (uint32_t)n0 * PITCH + bLane +
                          (uint32_t)(k * 16) * 2);
                mma16816(&acc[np][0], a, b[0], b[1]);   // units n0..n0+7
                mma16816(&acc[np][4], a, b[2], b[3]);   // units n0+8..n0+15
            }
        }
        __syncthreads();   // all ldmatrix reads of H done before h-stores

        const int tok0 = tok_s[row0 * 17 + t];
        const int tok1 = tok_s[row1 * 17 + t];

        #pragma unroll
        for (int uh = 0; uh < 2; uh++) {
            #pragma unroll
            for (int tau = 0; tau < 2; tau++) {
                #pragma unroll
                for (int rho = 0; rho < 2; rho++) {
                    const int e = rho ? row1 : row0;
                    const int tok = rho ? tok1 : tok0;
                    const int ubase = ug * 32 + uh * 16 + tau * 8 + 2 * t4;
                    const float* Pr = g_P + tok * G4 + ubase;
                    float2 Pi = *(const float2*)(Pr);
                    float2 Pf = *(const float2*)(Pr + 128);
                    float2 Pg = *(const float2*)(Pr + 256);
                    float2 Po = *(const float2*)(Pr + 384);
                    float hn[2];
                    #pragma unroll
                    for (int dl = 0; dl < 2; dl++) {
                        const int j = tau * 4 + rho * 2 + dl;
                        const int ci = uh * 8 + tau * 4 + rho * 2 + dl;
                        float vi = acc[0 + uh][j] + (dl ? Pi.y : Pi.x);
                        float vf = acc[2 + uh][j] + (dl ? Pf.y : Pf.x);
                        float vg = acc[4 + uh][j] + (dl ? Pg.y : Pg.x);
                        float vo = acc[6 + uh][j] + (dl ? Po.y : Po.x);
                        float cj = sigt(vf) * c[ci] + sigt(vi) * tanha(vg);
                        c[ci] = cj;
                        hn[dl] = sigt(vo) * tanha(cj);
                    }
                    uint32_t pr;
                    asm("cvt.rn.bf16x2.f32 %0, %1, %2;"
                        : "=r"(pr) : "f"(hn[1]), "f"(hn[0]));
                    *(uint32_t*)(smem + OFF_H + e * PITCH + ubase * 2) = pr;
                }
            }
        }
        __syncthreads();   // h stores visible before next step's ldmatrix
    }

    // MLP head: feat = relu(h_fwd @ W1[:128] + Tb[last_tok]); scalar = relu(feat@W2+b2)
    {
        const int e = tid >> 3;                 // 0..63
        const int fq = tid & 7;                 // feat group of 4
        const int tok15 = tok_s[e * 17 + 15];
        float acc4[4];
        {
            const float4 tb = *(const float4*)(g_Tb + tok15 * 32 + fq * 4);
            acc4[0] = tb.x; acc4[1] = tb.y; acc4[2] = tb.z; acc4[3] = tb.w;
        }
        const char* hrow = smem + OFF_H + e * PITCH;
        #pragma unroll 4
        for (int k = 0; k < HD; k++) {
            float hk = __bfloat162float(*(const __nv_bfloat16*)(hrow + k * 2));
            const float4 w = *(const float4*)(W1 + k * 32 + fq * 4);
            acc4[0] += hk * w.x; acc4[1] += hk * w.y;
            acc4[2] += hk * w.z; acc4[3] += hk * w.w;
        }
        #pragma unroll
        for (int i = 0; i < 4; i++) Fs[e * 33 + fq * 4 + i] = fmaxf(acc4[i], 0.f);
    }
    __syncthreads();
    if (tid < EPB) {
        float s = b2[0];
        #pragma unroll
        for (int f = 0; f < 32; f++) s += Fs[tid * 33 + f] * W2[f];
        g_ea[ebase + tid] = fmaxf(s, 0.f);
    }
}

// ------------------------- node argmax (first 53 cols, first-max wins) -------
__global__ void k_argmax(const float* __restrict__ x)
{
    const int gw = (blockIdx.x * blockDim.x + threadIdx.x) >> 5;
    const int lane = threadIdx.x & 31;
    if (gw >= NN) return;
    const float* row = x + (size_t)gw * DD;
    float best = -3.4e38f;
    int bidx = 0x7fffffff;
    for (int i = lane; i < NSID; i += 32) {
        float v = row[i];
        if (v > best) { best = v; bidx = i; }
    }
    #pragma unroll
    for (int off = 16; off; off >>= 1) {
        float ov = __shfl_down_sync(0xffffffffu, best, off);
        int oi = __shfl_down_sync(0xffffffffu, bidx, off);
        if (ov > best || (ov == best && oi < bidx)) { best = ov; bidx = oi; }
    }
    if (lane == 0) g_nid[gw] = bidx;
}

// ------------------------- copy x into padded workspace ----------------------
__global__ void k_copy(const float* __restrict__ x)
{
    const int i = blockIdx.x * blockDim.x + threadIdx.x;
    const int stride = gridDim.x * blockDim.x;
    for (int idx = i; idx < NN * DP; idx += stride) {
        int n = idx / DP, d = idx - n * DP;
        g_xw[idx] = (d < DD) ? x[n * DD + d] : 0.f;
    }
}

// ------------------------- scatter writes (last edge index wins) -------------
__global__ void k_win(const int* __restrict__ ei)
{
    const int e = blockIdx.x * blockDim.x + threadIdx.x;
    if (e >= NE) return;
    int src = ei[e], dst = ei[NE + e];
    atomicMax(&g_win[dst * NSID + g_nid[src]], e);
    atomicMax(&g_win[NN * NSID + src * NSID + g_nid[dst]], e);
}

__global__ void k_wr(const int* __restrict__ ei)
{
    const int e = blockIdx.x * blockDim.x + threadIdx.x;
    if (e >= NE) return;
    int src = ei[e], dst = ei[NE + e];
    int sid = g_nid[src], tgt = g_nid[dst];
    float v = g_ea[e];
    if (g_win[dst * NSID + sid] == e)             g_xw[(size_t)dst * DP + IN_COL + sid] = v;
    if (g_win[NN * NSID + src * NSID + tgt] == e) g_xw[(size_t)src * DP + OUT_COL + tgt] = v;
}

// ------------------------- GEMM: C = xw @ B + bias (pads -> 0) ---------------
#define BM 64
#define BN 64
#define BK 16
__global__ __launch_bounds__(256) void k_gemm(const float* __restrict__ B,
                                              const float* __restrict__ bias,
                                              int sel)
{
    __shared__ __align__(16) float As[BK * BM];
    __shared__ __align__(16) float Bs[BK * BN];
    float* C = sel ? g_xr : g_xl;
    const int tid = threadIdx.x;
    const int mBase = blockIdx.y * BM;
    const int nBase = blockIdx.x * BN;
    const int ty = tid >> 4, tx = tid & 15;
    const int arow = tid >> 2;
    const int akq = tid & 3;
    const float4* As4 = (const float4*)As;
    const float4* Bs4 = (const float4*)Bs;

    float acc[4][4];
    #pragma unroll
    for (int i = 0; i < 4; i++)
        #pragma unroll
        for (int j = 0; j < 4; j++) acc[i][j] = 0.f;

    for (int k0 = 0; k0 < DD; k0 += BK) {
        int gm = mBase + arow;
        float4 av = make_float4(0.f, 0.f, 0.f, 0.f);
        if (gm < NN) av = *(const float4*)(g_xw + (size_t)gm * DP + k0 + akq * 4);
        As[(akq * 4 + 0) * BM + arow] = av.x;
        As[(akq * 4 + 1) * BM + arow] = av.y;
        As[(akq * 4 + 2) * BM + arow] = av.z;
        As[(akq * 4 + 3) * BM + arow] = av.w;
        #pragma unroll
        for (int i = 0; i < 4; i++) {
            int idx = tid + 256 * i;
            int kk = idx >> 6, jj = idx & 63;
            int gk = k0 + kk, gj = nBase + jj;
            Bs[idx] = (gk < DD && gj < DD) ? B[gk * DD + gj] : 0.f;
        }
        __syncthreads();
        #pragma unroll
        for (int kk = 0; kk < BK; kk++) {
            float4 a = As4[kk * 16 + ty];
            float4 b = Bs4[kk * 16 + tx];
            acc[0][0] += a.x * b.x; acc[0][1] += a.x * b.y; acc[0][2] += a.x * b.z; acc[0][3] += a.x * b.w;
            acc[1][0] += a.y * b.x; acc[1][1] += a.y * b.y; acc[1][2] += a.y * b.z; acc[1][3] += a.y * b.w;
            acc[2][0] += a.z * b.x; acc[2][1] += a.z * b.y; acc[2][2] += a.z * b.z; acc[2][3] += a.z * b.w;
            acc[3][0] += a.w * b.x; acc[3][1] += a.w * b.y; acc[3][2] += a.w * b.z; acc[3][3] += a.w * b.w;
        }
        __syncthreads();
    }
    #pragma unroll
    for (int i = 0; i < 4; i++) {
        int gm = mBase + ty * 4 + i;
        if (gm >= NN) continue;
        #pragma unroll
        for (int j = 0; j < 4; j++) {
            int gj = nBase + tx * 4 + j;
            float bv = (gj < DD) ? bias[gj] : 0.f;
            C[(size_t)gm * DP + gj] = acc[i][j] + bv;
        }
    }
}

// ------------------------- GATv2 edge passes ---------------------------------
__global__ void k_score(const int* __restrict__ ei, const float* __restrict__ att)
{
    const int gw = (blockIdx.x * blockDim.x + threadIdx.x) >> 5;
    const int lane = threadIdx.x & 31;
    if (gw >= NE) return;
    int src = ei[gw], dst = ei[NE + gw];
    const float4* pl = (const float4*)(g_xl + (size_t)src * DP);
    const float4* pr = (const float4*)(g_xr + (size_t)dst * DP);
    float s = 0.f;
    #pragma unroll
    for (int i = 0; i < 3; i++) {
        int c4 = lane + 32 * i;
        float4 a = pl[c4];
        float4 b = pr[c4];
        float4 m;
        m.x = lrelu(a.x + b.x); m.y = lrelu(a.y + b.y);
        m.z = lrelu(a.z + b.z); m.w = lrelu(a.w + b.w);
        int cc = c4 * 4;
        if (cc + 3 < DD) {
            s += m.x * att[cc] + m.y * att[cc + 1] + m.z * att[cc + 2] + m.w * att[cc + 3];
        } else {
            if (cc     < DD) s += m.x * att[cc];
            if (cc + 1 < DD) s += m.y * att[cc + 1];
            if (cc + 2 < DD) s += m.z * att[cc + 2];
        }
    }
    #pragma unroll
    for (int off = 16; off; off >>= 1) s += __shfl_xor_sync(0xffffffffu, s, off);
    if (lane == 0) {
        g_esc[gw] = s;
        atomicMax(&g_emax[dst], encf(s));
    }
}

__global__ void k_exp(const int* __restrict__ ei)
{
    const int e = blockIdx.x * blockDim.x + threadIdx.x;
    if (e >= NE) return;
    int dst = ei[NE + e];
    float mx = decf(g_emax[dst]);
    float ex = __expf(g_esc[e] - mx);
    g_esc[e] = ex;
    atomicAdd(&g_denom[dst], ex);
}

__global__ void k_agg(const int* __restrict__ ei)
{
    const int gw = (blockIdx.x * blockDim.x + threadIdx.x) >> 5;
    const int lane = threadIdx.x & 31;
    if (gw >= NE) return;
    int src = ei[gw], dst = ei[NE + gw];
    float alpha = g_esc[gw] / (g_denom[dst] + 1e-16f);
    const float4* pl = (const float4*)(g_xl + (size_t)src * DP);
    float* pa = g_agg + (size_t)dst * DP;
    #pragma unroll
    for (int i = 0; i < 3; i++) {
        int c4 = lane + 32 * i;
        float4 v = pl[c4];
        atomicAdd(pa + c4 * 4 + 0, alpha * v.x);
        atomicAdd(pa + c4 * 4 + 1, alpha * v.y);
        atomicAdd(pa + c4 * 4 + 2, alpha * v.z);
        atomicAdd(pa + c4 * 4 + 3, alpha * v.w);
    }
}

// ------------------------- epilogue ------------------------------------------
__global__ void k_out(const float* __restrict__ bias, float* __restrict__ out, int half)
{
    const int i = blockIdx.x * blockDim.x + threadIdx.x;
    const int stride = gridDim.x * blockDim.x;
    for (int idx = i; idx < NN * DD; idx += stride) {
        int n = idx / DD, d = idx - n * DD;
        float v = g_agg[n * DP + d] + bias[d] + g_xw[n * DP + d];
        out[(size_t)n * (2 * DD) + half * DD + d] = fmaxf(v, 0.f);
    }
}

// ------------------------- launch --------------------------------------------
extern "C" void kernel_launch(void* const* d_in, const int* in_sizes, int n_in,
                              void* d_out, int out_size)
{
    (void)in_sizes; (void)n_in; (void)out_size;
    const float* fx    = (const float*)d_in[0];
    const float* bx    = (const float*)d_in[1];
    const int*   f_ei  = (const int*)d_in[2];
    const int*   b_ei  = (const int*)d_in[3];
    const int*   f_tok = (const int*)d_in[4];
    const int*   b_tok = (const int*)d_in[5];
    const float* embed = (const float*)d_in[6];
    const float* Wih_f = (const float*)d_in[7];
    const float* Whh_f = (const float*)d_in[8];
    const float* bih_f = (const float*)d_in[9];
    const float* bhh_f = (const float*)d_in[10];
    const float* Wih_r = (const float*)d_in[11];
    const float* bih_r = (const float*)d_in[13];
    const float* bhh_r = (const float*)d_in[14];
    const float* W1    = (const float*)d_in[15];
    const float* b1    = (const float*)d_in[16];
    const float* W2    = (const float*)d_in[17];
    const float* b2    = (const float*)d_in[18];
    float* out = (float*)d_out;

    cudaFuncSetAttribute(k_lstm, cudaFuncAttributeMaxDynamicSharedMemorySize, LSTM_SMEM);

    k_tables<<<VOCAB, 512>>>(embed, Wih_f, bih_f, bhh_f, Whh_f, Wih_r, bih_r, bhh_r, W1, b1);

    for (int g = 0; g < 2; g++) {
        const float* x    = g ? bx : fx;
        const int*   ei   = g ? b_ei : f_ei;
        const int*   tok  = g ? b_tok : f_tok;
        const float* Wl   = (const float*)d_in[19 + 6 * g + 0];
        const float* bl   = (const float*)d_in[19 + 6 * g + 1];
        const float* Wr   = (const float*)d_in[19 + 6 * g + 2];
        const float* br   = (const float*)d_in[19 + 6 * g + 3];
        const float* att  = (const float*)d_in[19 + 6 * g + 4];
        const float* bias = (const float*)d_in[19 + 6 * g + 5];

        k_init<<<1024, 256>>>();
        k_lstm<<<NE / EPB, LSTM_THREADS, LSTM_SMEM>>>(tok, W1, W2, b2);
        k_argmax<<<(NN * 32 + 255) / 256, 256>>>(x);
        k_copy<<<2048, 256>>>(x);
        k_win<<<(NE + 255) / 256, 256>>>(ei);
        k_wr<<<(NE + 255) / 256, 256>>>(ei);
        dim3 ggrid(DP / BN, (NN + BM - 1) / BM);
        k_gemm<<<ggrid, 256>>>(Wl, bl, 0);
        k_gemm<<<ggrid, 256>>>(Wr, br, 1);
        k_score<<<NE / 8, 256>>>(ei, att);
        k_exp<<<(NE + 255) / 256, 256>>>(ei);
        k_agg<<<NE / 8, 256>>>(ei);
        k_out<<<4096, 256>>>(bias, out, g);
    }
}